// round 6
// baseline (speedup 1.0000x reference)
#include <cuda_runtime.h>
#include <cstdint>
#include <cstddef>

#define BB  8
#define TT  4096
#define CC  1024
#define HSS 128
#define M_TOT (BB*TT)
#define SP  132
#define S_X 36
#define S_W 136

typedef unsigned long long u64;
typedef uint32_t u32;

__device__ float g_q[BB*TT*HSS];
__device__ float g_k[BB*TT*HSS];
__device__ float g_v[BB*TT*HSS];

// ---------------- helpers ----------------
__device__ __forceinline__ u32 tf32r(float x){
    u32 r; asm("cvt.rna.tf32.f32 %0, %1;" : "=r"(r) : "f"(x)); return r;
}
__device__ __forceinline__ float4 cvt4(float4 v){
    float4 o;
    o.x = __uint_as_float(tf32r(v.x)); o.y = __uint_as_float(tf32r(v.y));
    o.z = __uint_as_float(tf32r(v.z)); o.w = __uint_as_float(tf32r(v.w));
    return o;
}
__device__ __forceinline__ void mma8(float* d, const u32* a, u32 b0, u32 b1){
    asm volatile("mma.sync.aligned.m16n8k8.row.col.f32.tf32.tf32.f32 "
        "{%0,%1,%2,%3}, {%4,%5,%6,%7}, {%8,%9}, {%0,%1,%2,%3};"
        : "+f"(d[0]), "+f"(d[1]), "+f"(d[2]), "+f"(d[3])
        : "r"(a[0]), "r"(a[1]), "r"(a[2]), "r"(a[3]), "r"(b0), "r"(b1));
}
__device__ __forceinline__ u32 s2u(const void* p){
    u32 a; asm("{ .reg .u64 t; cvta.to.shared.u64 t, %1; cvt.u32.u64 %0, t; }" : "=r"(a) : "l"(p));
    return a;
}
__device__ __forceinline__ void cpa16(u32 dst, const void* src){
    asm volatile("cp.async.cg.shared.global [%0], [%1], 16;" :: "r"(dst), "l"(src) : "memory");
}
#define CP_COMMIT() asm volatile("cp.async.commit_group;" ::: "memory")
#define CP_WAIT0()  asm volatile("cp.async.wait_group 0;" ::: "memory")

// ---------------------------------------------------------------------------
// QKV projection (unchanged from R5 — measured tensor-saturated).
// ---------------------------------------------------------------------------
__global__ __launch_bounds__(256, 2)
void qkv_mma_kernel(const float* __restrict__ x,
                    const float* __restrict__ Wq,
                    const float* __restrict__ Wk,
                    const float* __restrict__ Wv)
{
    extern __shared__ float qsm[];
    const int which = blockIdx.y;
    const float* __restrict__ W = (which==0) ? Wq : (which==1) ? Wk : Wv;
    float* __restrict__ out = (which==0) ? g_q : (which==1) ? g_k : g_v;
    const float scale = (which==0) ? 0.08838834764831845f : 1.0f;

    const int m0  = blockIdx.x * 128;
    const int tid = threadIdx.x;
    const int wid  = tid >> 5;
    const int lane = tid & 31;
    const int wm = wid >> 1, wn = wid & 1;
    const int g = lane >> 2, t = lane & 3;
    const int m0b = 32*wm;
    const int nb  = 64*wn;

    const u32 sbase = s2u(qsm);

    float o[2][8][4];
    #pragma unroll
    for (int i = 0; i < 2; i++)
        #pragma unroll
        for (int j = 0; j < 8; j++)
            #pragma unroll
            for (int q = 0; q < 4; q++) o[i][j][q] = 0.f;

    {
        #pragma unroll
        for (int l = 0; l < 4; l++) {
            int f = tid + (l<<8);
            int row = f >> 3, q4 = f & 7;
            cpa16(sbase + (u32)((row*S_X + (q4<<2))<<2),
                  x + (size_t)(m0+row)*CC + (q4<<2));
        }
        #pragma unroll
        for (int l = 0; l < 4; l++) {
            int f = tid + (l<<8);
            int kk = f >> 5, n4 = f & 31;
            cpa16(sbase + (u32)((9216 + kk*S_W + (n4<<2))<<2),
                  W + (size_t)kk*HSS + (n4<<2));
        }
        CP_COMMIT();
    }

    for (int ic = 0; ic < 32; ic++) {
        const int buf = ic & 1;
        CP_WAIT0();
        __syncthreads();
        if (ic < 31) {
            const int k0n = (ic+1) << 5;
            const u32 xd = sbase + (u32)(((buf^1)*4608)<<2);
            const u32 wd = sbase + (u32)((9216 + (buf^1)*4352)<<2);
            #pragma unroll
            for (int l = 0; l < 4; l++) {
                int f = tid + (l<<8);
                int row = f >> 3, q4 = f & 7;
                cpa16(xd + (u32)((row*S_X + (q4<<2))<<2),
                      x + (size_t)(m0+row)*CC + k0n + (q4<<2));
            }
            #pragma unroll
            for (int l = 0; l < 4; l++) {
                int f = tid + (l<<8);
                int kk = f >> 5, n4 = f & 31;
                cpa16(wd + (u32)((kk*S_W + (n4<<2))<<2),
                      W + (size_t)(k0n+kk)*HSS + (n4<<2));
            }
            CP_COMMIT();
        }

        const float* Xr = qsm + buf*4608;
        const float* Wr = qsm + 9216 + buf*4352;

        #pragma unroll
        for (int kk = 0; kk < 4; kk++) {
            const int k = kk << 3;
            u32 ah[2][4], al[2][4];
            #pragma unroll
            for (int mb = 0; mb < 2; mb++) {
                const float* ph = &Xr[(m0b + 16*mb + g)*S_X + k + t];
                float r0 = ph[0], r1 = ph[8*S_X], r2 = ph[4], r3 = ph[8*S_X + 4];
                ah[mb][0] = tf32r(r0); ah[mb][1] = tf32r(r1);
                ah[mb][2] = tf32r(r2); ah[mb][3] = tf32r(r3);
                al[mb][0] = tf32r(r0 - __uint_as_float(ah[mb][0]));
                al[mb][1] = tf32r(r1 - __uint_as_float(ah[mb][1]));
                al[mb][2] = tf32r(r2 - __uint_as_float(ah[mb][2]));
                al[mb][3] = tf32r(r3 - __uint_as_float(ah[mb][3]));
            }
            #pragma unroll
            for (int j = 0; j < 8; j++) {
                const float* bp = &Wr[(k + t)*S_W + nb + 8*j + g];
                u32 b0 = tf32r(bp[0]);
                u32 b1 = tf32r(bp[4*S_W]);
                mma8(o[0][j], ah[0], b0, b1);
                mma8(o[1][j], ah[1], b0, b1);
                mma8(o[0][j], al[0], b0, b1);
                mma8(o[1][j], al[1], b0, b1);
            }
        }
    }

    #pragma unroll
    for (int mb = 0; mb < 2; mb++)
        #pragma unroll
        for (int h = 0; h < 2; h++) {
            const int row = m0 + m0b + 16*mb + 8*h + g;
            #pragma unroll
            for (int j = 0; j < 8; j++) {
                float v0 = o[mb][j][2*h+0] * scale;
                float v1 = o[mb][j][2*h+1] * scale;
                *(float2*)&out[(size_t)row*HSS + nb + 8*j + 2*t] = make_float2(v0, v1);
            }
        }
}

// ---------------------------------------------------------------------------
// Banded attention: warp-owned rows, register-resident P, ONE barrier/iter.
// 8 warps x 16 rows; each warp computes full BN=64 S-cols and full 128 O-cols.
// P converted D-frag -> A-frag via quad shuffles (no smem round-trip).
// smem floats: Q[0,16896) K0@16896 K1@25344 V0@33792 V1@42240  (202752 B)
// ---------------------------------------------------------------------------
__global__ __launch_bounds__(256, 1)
void attn_mma_kernel(float* __restrict__ out)
{
    extern __shared__ float sm[];
    float* Qs = sm;

    const int tid  = threadIdx.x;
    const int wid  = tid >> 5;
    const int lane = tid & 31;
    const int g = lane >> 2, t = lane & 3;
    const int rA = 16*wid + g;          // local row of d0/d1
    const int srcA = (lane & 28) | (t >> 1);
    const int srcB = srcA + 2;
    const int selb = t & 1;

    const int b  = blockIdx.x & 7;
    const int qt = 31 - (blockIdx.x >> 3);
    const int r0 = qt << 7;

    const u32 sbase = s2u(sm);

    const float* __restrict__ kbase = g_k + (size_t)b*TT*HSS;
    const float* __restrict__ vbase = g_v + (size_t)b*TT*HSS;

    const int rmax = r0 + 127;
    const int ct0 = (2047 - (rmax>>1)) >> 6;
    const int ct1 = (2047 + ((rmax+1)>>1)) >> 6;

    // prologue: stream first K/V tile into buf 0
    {
        const int c0 = ct0 << 6;
        const float* kb = kbase + (size_t)c0*HSS;
        const float* vb = vbase + (size_t)c0*HSS;
        #pragma unroll
        for (int l = 0; l < 8; l++) {
            int f = tid + (l<<8);
            int row = f >> 5, q4 = f & 31;
            u32 off = (u32)((row*SP + (q4<<2))<<2);
            cpa16(sbase + (16896u<<2) + off, kb + row*HSS + (q4<<2));
            cpa16(sbase + (33792u<<2) + off, vb + row*HSS + (q4<<2));
        }
        CP_COMMIT();
    }

    // Q tile (once), rna-rounded
    const float* __restrict__ qb = g_q + ((size_t)b*TT + r0)*HSS;
    #pragma unroll
    for (int l = 0; l < 16; l++) {
        int f = tid + (l<<8);
        int row = f >> 5, q4 = f & 31;
        float4 v = cvt4(*(const float4*)(qb + row*HSS + (q4<<2)));
        *(float4*)&Qs[row*SP + (q4<<2)] = v;
    }

    // band bounds for this thread's 2 rows
    const int grA = r0 + rA, grB = grA + 8;
    const int loA = 2047 - (grA >> 1), hiA = 2047 + ((grA + 1) >> 1);
    const int loB = 2047 - (grB >> 1), hiB = 2047 + ((grB + 1) >> 1);

    float o[16][4];
    #pragma unroll
    for (int j = 0; j < 16; j++)
        #pragma unroll
        for (int q = 0; q < 4; q++) o[j][q] = 0.f;
    float lsumA = 0.f, lsumB = 0.f;

    int buf = 0;
    for (int ct = ct0; ct <= ct1; ct++, buf ^= 1) {
        CP_WAIT0();
        __syncthreads();     // tile[buf] ready; all warps done with buf^1

        if (ct < ct1) {
            const int c0n = (ct+1) << 6;
            const float* kb = kbase + (size_t)c0n*HSS;
            const float* vb = vbase + (size_t)c0n*HSS;
            const u32 kd = sbase + ((u32)(16896 + (buf^1)*8448)<<2);
            const u32 vd = sbase + ((u32)(33792 + (buf^1)*8448)<<2);
            #pragma unroll
            for (int l = 0; l < 8; l++) {
                int f = tid + (l<<8);
                int row = f >> 5, q4 = f & 31;
                u32 off = (u32)((row*SP + (q4<<2))<<2);
                cpa16(kd + off, kb + row*HSS + (q4<<2));
                cpa16(vd + off, vb + row*HSS + (q4<<2));
            }
            CP_COMMIT();
        }

        const float* Kb = sm + 16896 + buf*8448;
        const float* Vb = sm + 33792 + buf*8448;
        const int c0 = ct << 6;

        // ---- MMA1: S(16x64 per warp) = Q @ K^T ----
        float s[8][4];
        #pragma unroll
        for (int j = 0; j < 8; j++)
            #pragma unroll
            for (int q = 0; q < 4; q++) s[j][q] = 0.f;

        #pragma unroll
        for (int kk = 0; kk < 16; kk++) {
            const int k0 = kk << 3;
            const float* qp = &Qs[rA*SP + k0 + t];
            u32 a[4];
            a[0] = __float_as_uint(qp[0]);
            a[1] = __float_as_uint(qp[8*SP]);
            a[2] = __float_as_uint(qp[4]);
            a[3] = __float_as_uint(qp[8*SP + 4]);
            #pragma unroll
            for (int j = 0; j < 8; j++) {
                const float* kp = &Kb[(8*j + g)*SP + k0 + t];
                u32 b0 = tf32r(kp[0]);
                u32 b1 = tf32r(kp[4]);
                mma8(s[j], a, b0, b1);
            }
        }

        // ---- mask + exp (tf32-rounded) + in-register D->A conversion ----
        u32 A[8][4];
        #pragma unroll
        for (int j = 0; j < 8; j++) {
            const int cb = c0 + 8*j + 2*t;
            float p0 = (cb   >= loA && cb   <= hiA) ? __expf(s[j][0]) : 0.f;
            float p1 = (cb+1 >= loA && cb+1 <= hiA) ? __expf(s[j][1]) : 0.f;
            float p2 = (cb   >= loB && cb   <= hiB) ? __expf(s[j][2]) : 0.f;
            float p3 = (cb+1 >= loB && cb+1 <= hiB) ? __expf(s[j][3]) : 0.f;
            u32 q0 = tf32r(p0), q1 = tf32r(p1), q2 = tf32r(p2), q3 = tf32r(p3);
            lsumA += __uint_as_float(q0) + __uint_as_float(q1);
            lsumB += __uint_as_float(q2) + __uint_as_float(q3);
            // quad butterfly: D cols {2t,2t+1} -> A cols {t, t+4}
            u32 v0a = __shfl_sync(0xffffffffu, q0, srcA);
            u32 v1a = __shfl_sync(0xffffffffu, q1, srcA);
            u32 v0b = __shfl_sync(0xffffffffu, q0, srcB);
            u32 v1b = __shfl_sync(0xffffffffu, q1, srcB);
            u32 w0a = __shfl_sync(0xffffffffu, q2, srcA);
            u32 w1a = __shfl_sync(0xffffffffu, q3, srcA);
            u32 w0b = __shfl_sync(0xffffffffu, q2, srcB);
            u32 w1b = __shfl_sync(0xffffffffu, q3, srcB);
            A[j][0] = selb ? v1a : v0a;
            A[j][2] = selb ? v1b : v0b;
            A[j][1] = selb ? w1a : w0a;
            A[j][3] = selb ? w1b : w0b;
        }

        // ---- MMA2: O(16x128 per warp) += P @ V ----
        #pragma unroll
        for (int jk = 0; jk < 8; jk++) {
            const int k0 = jk << 3;
            #pragma unroll
            for (int n2 = 0; n2 < 16; n2++) {
                const float* vp = &Vb[(k0 + t)*SP + 8*n2 + g];
                u32 b0 = tf32r(vp[0]);
                u32 b1 = tf32r(vp[4*SP]);
                mma8(o[n2], A[jk], b0, b1);
            }
        }
    }

    // ---- quad-reduce row sums (rows are warp-exclusive; no smem needed) ----
    lsumA += __shfl_xor_sync(0xffffffffu, lsumA, 1);
    lsumA += __shfl_xor_sync(0xffffffffu, lsumA, 2);
    lsumB += __shfl_xor_sync(0xffffffffu, lsumB, 1);
    lsumB += __shfl_xor_sync(0xffffffffu, lsumB, 2);
    const float invA = 1.0f / lsumA;
    const float invB = 1.0f / lsumB;

    float* __restrict__ obA = out + ((size_t)b*TT + grA)*HSS;
    float* __restrict__ obB = out + ((size_t)b*TT + grB)*HSS;
    #pragma unroll
    for (int n2 = 0; n2 < 16; n2++) {
        *(float2*)&obA[8*n2 + 2*t] = make_float2(o[n2][0]*invA, o[n2][1]*invA);
        *(float2*)&obB[8*n2 + 2*t] = make_float2(o[n2][2]*invB, o[n2][3]*invB);
    }
}

// ---------------------------------------------------------------------------
extern "C" void kernel_launch(void* const* d_in, const int* in_sizes, int n_in,
                              void* d_out, int out_size)
{
    const float* x  = (const float*)d_in[0];
    const float* Wq = (const float*)d_in[1];
    const float* Wk = (const float*)d_in[2];
    const float* Wv = (const float*)d_in[3];
    float* out = (float*)d_out;

    const int qsmem = 17920 * (int)sizeof(float);   // 71680 B
    cudaFuncSetAttribute(qkv_mma_kernel, cudaFuncAttributeMaxDynamicSharedMemorySize, qsmem);
    dim3 g1(M_TOT/128, 3);
    qkv_mma_kernel<<<g1, 256, qsmem>>>(x, Wq, Wk, Wv);

    const int smem = 50688 * (int)sizeof(float);    // 202752 B
    cudaFuncSetAttribute(attn_mma_kernel, cudaFuncAttributeMaxDynamicSharedMemorySize, smem);
    attn_mma_kernel<<<BB*32, 256, smem>>>(out);
}